// round 17
// baseline (speedup 1.0000x reference)
#include <cuda_runtime.h>
#include <cuda_fp16.h>
#include <cstdint>

#define NEG_INIT -1.0e9f

// ---------------------------------------------------------------------------
__device__ __forceinline__ unsigned enc_f(float f) {
    unsigned u = __float_as_uint(f);
    return (u & 0x80000000u) ? ~u : (u | 0x80000000u);
}
__device__ __forceinline__ float dec_f(unsigned e) {
    unsigned u = (e & 0x80000000u) ? (e & 0x7FFFFFFFu) : ~e;
    return __uint_as_float(u);
}
__device__ __forceinline__ float lrelu(float x) { return x >= 0.f ? x : 0.2f * x; }

__device__ unsigned g_gf[16384 * 128];   // encoded global_feats scratch (8 MB)

__device__ __forceinline__ uint32_t smem_u32(const void* p) {
    uint32_t a;
    asm("{ .reg .u64 t; cvta.to.shared.u64 t, %1; cvt.u32.u64 %0, t; }" : "=r"(a) : "l"(p));
    return a;
}

#define SWZ(x) ((x) ^ (((x) >> 3) & 0x70))

// 2-warp (64-thread) named barrier for wm-group: ids 1..4
#define BAR_GROUP(id) asm volatile("bar.sync %0, 64;" :: "r"(id) : "memory")

__device__ __forceinline__ void ldsm4(unsigned r[4], uint32_t addr) {
    asm volatile("ldmatrix.sync.aligned.m8n8.x4.shared.b16 {%0,%1,%2,%3}, [%4];"
                 : "=r"(r[0]), "=r"(r[1]), "=r"(r[2]), "=r"(r[3]) : "r"(addr));
}
// f16 k16 MMA (layer 2)
__device__ __forceinline__ void hmma(float d[4], const unsigned a[4],
                                     unsigned b0, unsigned b1) {
    asm volatile(
        "mma.sync.aligned.m16n8k16.row.col.f32.f16.f16.f32 "
        "{%0,%1,%2,%3}, {%4,%5,%6,%7}, {%8,%9}, {%0,%1,%2,%3};"
        : "+f"(d[0]), "+f"(d[1]), "+f"(d[2]), "+f"(d[3])
        : "r"(a[0]), "r"(a[1]), "r"(a[2]), "r"(a[3]), "r"(b0), "r"(b1));
}
// f16 k8 MMA (layer 1, single product)
__device__ __forceinline__ void hmma_f16k8(float d[4], unsigned a0, unsigned a1,
                                           unsigned b0) {
    asm volatile(
        "mma.sync.aligned.m16n8k8.row.col.f32.f16.f16.f32 "
        "{%0,%1,%2,%3}, {%4,%5}, {%6}, {%0,%1,%2,%3};"
        : "+f"(d[0]), "+f"(d[1]), "+f"(d[2]), "+f"(d[3])
        : "r"(a0), "r"(a1), "r"(b0));
}
__device__ __forceinline__ unsigned cvt_f16x2(float lo, float hi) {
    unsigned r;
    asm("cvt.rn.f16x2.f32 %0, %1, %2;" : "=r"(r) : "f"(hi), "f"(lo));
    return r;
}

// ---------------------------------------------------------------------------
// SMEM layout (bytes) - point kernel
// ---------------------------------------------------------------------------
#define OFF_B16   0          // [128n][64k] f16, SW128 (W2), 16384 B
#define OFF_A16   16384      // 2 x [128m][64k] f16, SW128 (layer-1 out), 32768 B
#define OFF_X     49152      // 4 x [128m][16B]: f16 k0-6 + k7=1.0
#define OFF_W1A   57344      // [64n][16B]: f16 k0-7 (k7 = b1)
#define OFF_B2    58368      // 128 floats
#define OFF_BIDX  58880      // 4 x 128 ints
#define SMEM_BYTES 60928

// ---------------------------------------------------------------------------
__global__ void init_gf_kernel(int total4) {
    int i = blockIdx.x * blockDim.x + threadIdx.x;
    if (i < total4) {
        unsigned e = enc_f(NEG_INIT);
        ((uint4*)g_gf)[i] = make_uint4(e, e, e, e);
    }
}

// ---------------------------------------------------------------------------
// input load + X staging helpers (half==0 warp of each group only)
// ---------------------------------------------------------------------------
__device__ __forceinline__ void load_pin(
    const float* __restrict__ fm, const int* __restrict__ bidx,
    const float* __restrict__ cond, int tile, int numTiles, int m, int N,
    float pin[7], int& pb)
{
    pb = -1;
    #pragma unroll
    for (int k = 0; k < 7; k++) pin[k] = 0.f;
    if (tile < numTiles) {
        const int row = tile * 128 + m;
        if (row < N) {
            pin[0] = fm[row * 3 + 0]; pin[1] = fm[row * 3 + 1]; pin[2] = fm[row * 3 + 2];
            pb = bidx[row];
            const float4 c4 = *(const float4*)(cond + pb * 4);
            pin[3] = c4.x; pin[4] = c4.y; pin[5] = c4.z; pin[6] = c4.w;
        }
    }
}

__device__ __forceinline__ void stage_x(char* smem, int slot, int m,
                                        const float pin[7], int pb)
{
    uint4 v;
    v.x = cvt_f16x2(pin[0], pin[1]);
    v.y = cvt_f16x2(pin[2], pin[3]);
    v.z = cvt_f16x2(pin[4], pin[5]);
    v.w = cvt_f16x2(pin[6], 1.0f);          // k7 = 1.0 (bias column)
    *(uint4*)(smem + OFF_X + slot * 2048 + m * 16) = v;
    ((int*)(smem + OFF_BIDX))[slot * 128 + m] = pb;
}

// ---------------------------------------------------------------------------
// Layer-1 for one tile: f16 MMA from X[slot], output to af (own k-half of
// the layer-2 A fragments) and to A16[abuf] (partner's k-half).
// ---------------------------------------------------------------------------
__device__ __forceinline__ void layer1_tile(
    char* smem, uint32_t sbase, int slot, uint32_t abuf,
    const unsigned wh[4], int wm, int wn, int lane, unsigned af[2][2][4])
{
    unsigned xh[4];
    ldsm4(xh, sbase + OFF_X + slot * 2048 + ((wm << 5) + lane) * 16);

    float d1[2][4][4];
    #pragma unroll
    for (int mt = 0; mt < 2; mt++)
        #pragma unroll
        for (int g = 0; g < 4; g++)
            #pragma unroll
            for (int e = 0; e < 4; e++) d1[mt][g][e] = 0.f;
    #pragma unroll
    for (int g = 0; g < 4; g++)
        #pragma unroll
        for (int mt = 0; mt < 2; mt++)
            hmma_f16k8(d1[mt][g], xh[mt * 2], xh[mt * 2 + 1], wh[g]);

    #pragma unroll
    for (int mt = 0; mt < 2; mt++)
        #pragma unroll
        for (int j = 0; j < 2; j++) {
            af[mt][j][0] = cvt_f16x2(lrelu(d1[mt][2 * j][0]),     lrelu(d1[mt][2 * j][1]));
            af[mt][j][1] = cvt_f16x2(lrelu(d1[mt][2 * j][2]),     lrelu(d1[mt][2 * j][3]));
            af[mt][j][2] = cvt_f16x2(lrelu(d1[mt][2 * j + 1][0]), lrelu(d1[mt][2 * j + 1][1]));
            af[mt][j][3] = cvt_f16x2(lrelu(d1[mt][2 * j + 1][2]), lrelu(d1[mt][2 * j + 1][3]));
        }
    #pragma unroll
    for (int mt = 0; mt < 2; mt++) {
        const int r0 = (wm << 5) + (mt << 4) + (lane >> 2);
        const int r1 = r0 + 8;
        #pragma unroll
        for (int g = 0; g < 4; g++) {
            const int c = (wn << 5) + (g << 3) + ((lane & 3) << 1);
            *(unsigned*)(smem + abuf + r0 * 128 +
                         ((((c >> 3) ^ (r0 & 7)) & 7) << 4) + ((c & 7) << 1)) =
                af[mt][g >> 1][(g & 1) << 1];
            *(unsigned*)(smem + abuf + r1 * 128 +
                         ((((c >> 3) ^ (r1 & 7)) & 7) << 4) + ((c & 7) << 1)) =
                af[mt][g >> 1][((g & 1) << 1) + 1];
        }
    }
}

// ---------------------------------------------------------------------------
// Persistent fused point kernel, cross-tile pipelined:
//   own-L2(i) [af from last iter] -> BAR -> partner-L2(i) -> L1(i+1)->af
//   -> stage X(i+3) -> epilogue(i).  One group barrier per tile.
// ---------------------------------------------------------------------------
__global__ __launch_bounds__(256, 2) void point_kernel(
    const float* __restrict__ fm,   const int* __restrict__ bidx,
    const float* __restrict__ cond, const float* __restrict__ W1,
    const float* __restrict__ b1,   const float* __restrict__ W2,
    const float* __restrict__ b2,   int N, int numTiles)
{
    extern __shared__ char smem[];
    const uint32_t sbase = smem_u32(smem);
    const int t    = threadIdx.x;
    const int wid  = t >> 5;
    const int lane = t & 31;

    float* b2s = (float*)(smem + OFF_B2);
    int*   bix = (int*)(smem + OFF_BIDX);

    for (int e = t; e < 4096; e += 256) {          // W2 -> B16 f16 [n][k] SW128
        int n = e >> 5, k2 = e & 31;
        float w0 = W2[(2 * k2) * 128 + n];
        float w1 = W2[(2 * k2 + 1) * 128 + n];
        unsigned off = (unsigned)(n * 128 + k2 * 4);
        *(unsigned*)(smem + OFF_B16 + SWZ(off)) = cvt_f16x2(w0, w1);
    }
    if (t < 64) {                                   // W1 (+bias as k7) f16
        uint4 v;
        v.x = cvt_f16x2(W1[0 * 64 + t], W1[1 * 64 + t]);
        v.y = cvt_f16x2(W1[2 * 64 + t], W1[3 * 64 + t]);
        v.z = cvt_f16x2(W1[4 * 64 + t], W1[5 * 64 + t]);
        v.w = cvt_f16x2(W1[6 * 64 + t], b1[t]);
        *(uint4*)(smem + OFF_W1A + t * 16) = v;
    }
    if (t < 128) b2s[t] = b2[t];

    const int m    = t & 127;
    const int half = t >> 7;
    const int wm   = wid & 3;
    const int wn   = wid >> 2;
    const int gbar = 1 + wm;
    const int G    = gridDim.x;

    // ---- prologue: stage slots 0..2 (tiles it=0..2); hold pin for it=3 ----
    int tile = blockIdx.x;
    float pin[7]; int pb = -1;
    if (half == 0) {
        load_pin(fm, bidx, cond, tile, numTiles, m, N, pin, pb);
        stage_x(smem, 0, m, pin, pb);
        load_pin(fm, bidx, cond, tile + G, numTiles, m, N, pin, pb);
        stage_x(smem, 1, m, pin, pb);
        load_pin(fm, bidx, cond, tile + 2 * G, numTiles, m, N, pin, pb);
        stage_x(smem, 2, m, pin, pb);
        load_pin(fm, bidx, cond, tile + 3 * G, numTiles, m, N, pin, pb);
    }
    __syncthreads();   // weights + X slots 0..2 visible to all

    // loop-invariant W1 fragments + layer1 for tile it=0 (A buffer 0)
    unsigned wh[4];
    ldsm4(wh, sbase + OFF_W1A + ((wn << 5) + lane) * 16);
    unsigned af[2][2][4];
    layer1_tile(smem, sbase, 0, OFF_A16, wh, wm, wn, lane, af);

    int it = 0;
    while (tile < numTiles) {
        const int slot = it & 3;
        const uint32_t abuf = OFF_A16 + (unsigned)(it & 1) * 16384u;
        const int brow = (wn << 6) + (lane & 7) + ((lane >> 4) << 3);

        float d[2][8][4];
        #pragma unroll
        for (int mi = 0; mi < 2; mi++)
            #pragma unroll
            for (int ni = 0; ni < 8; ni++)
                #pragma unroll
                for (int e = 0; e < 4; e++) d[mi][ni][e] = 0.f;

        // ---- own k-half L2(i): af from previous iteration / prologue ----
        #pragma unroll
        for (int j = 0; j < 2; j++) {
            const int ks = 2 * wn + j;
            int bkch = (ks << 1) + ((lane >> 3) & 1);
            uint32_t boff = (uint32_t)(brow * 128 + (((bkch ^ (brow & 7)) & 7) << 4));
            unsigned bf[4][4];
            #pragma unroll
            for (int g = 0; g < 4; g++) ldsm4(bf[g], sbase + OFF_B16 + boff + g * 2048);
            #pragma unroll
            for (int g = 0; g < 4; g++) {
                #pragma unroll
                for (int mi = 0; mi < 2; mi++) {
                    hmma(d[mi][2 * g + 0], af[mi][j], bf[g][0], bf[g][1]);
                    hmma(d[mi][2 * g + 1], af[mi][j], bf[g][2], bf[g][3]);
                }
            }
        }

        BAR_GROUP(gbar);   // partner A16 half (tile i) + staged X/bix visible

        // ---- partner k-half L2(i): A via ldsm from A16[abuf] ----
        #pragma unroll
        for (int j = 0; j < 2; j++) {
            const int ks = 2 * (1 - wn) + j;
            int arow = (wm << 5) + (lane & 15);
            int akch = (ks << 1) + (lane >> 4);
            uint32_t aoff = (uint32_t)(arow * 128 + (((akch ^ (arow & 7)) & 7) << 4));
            unsigned ap[2][4];
            ldsm4(ap[0], sbase + abuf + aoff);
            ldsm4(ap[1], sbase + abuf + aoff + 16 * 128);
            int bkch = (ks << 1) + ((lane >> 3) & 1);
            uint32_t boff = (uint32_t)(brow * 128 + (((bkch ^ (brow & 7)) & 7) << 4));
            unsigned bf[4][4];
            #pragma unroll
            for (int g = 0; g < 4; g++) ldsm4(bf[g], sbase + OFF_B16 + boff + g * 2048);
            #pragma unroll
            for (int g = 0; g < 4; g++) {
                #pragma unroll
                for (int mi = 0; mi < 2; mi++) {
                    hmma(d[mi][2 * g + 0], ap[mi], bf[g][0], bf[g][1]);
                    hmma(d[mi][2 * g + 1], ap[mi], bf[g][2], bf[g][3]);
                }
            }
        }

        // ---- layer 1 for tile i+1 (overlaps epilogue latency) ----
        layer1_tile(smem, sbase, (it + 1) & 3,
                    OFF_A16 + (unsigned)((it + 1) & 1) * 16384u,
                    wh, wm, wn, lane, af);

        // ---- stage X for tile i+3; issue loads for tile i+4 ----
        if (half == 0) {
            stage_x(smem, (it + 3) & 3, m, pin, pb);
            load_pin(fm, bidx, cond, tile + 4 * G, numTiles, m, N, pin, pb);
        }

        // ---- epilogue(i): in-register segmented max + atomics ----
        {
            const int base  = slot * 128 + (wm << 5);
            const int rA    = lane >> 2;
            const int bfirst = bix[base];
            const int blast  = bix[base + 31];
            if (bfirst == blast) {
                float acc[16];
                #pragma unroll
                for (int ni = 0; ni < 8; ni++) {
                    float a0 = fmaxf(fmaxf(d[0][ni][0], d[0][ni][2]),
                                     fmaxf(d[1][ni][0], d[1][ni][2]));
                    float a1 = fmaxf(fmaxf(d[0][ni][1], d[0][ni][3]),
                                     fmaxf(d[1][ni][1], d[1][ni][3]));
                    acc[2 * ni] = a0; acc[2 * ni + 1] = a1;
                }
                #pragma unroll
                for (int q = 0; q < 16; q++) {
                    acc[q] = fmaxf(acc[q], __shfl_xor_sync(0xFFFFFFFFu, acc[q], 4));
                    acc[q] = fmaxf(acc[q], __shfl_xor_sync(0xFFFFFFFFu, acc[q], 8));
                    acc[q] = fmaxf(acc[q], __shfl_xor_sync(0xFFFFFFFFu, acc[q], 16));
                }
                if (lane < 4 && bfirst >= 0) {
                    #pragma unroll
                    for (int ni = 0; ni < 8; ni++) {
                        const int c = (wn << 6) + (ni << 3) + (lane << 1);
                        float y0 = lrelu(acc[2 * ni]     + b2s[c]);
                        float y1 = lrelu(acc[2 * ni + 1] + b2s[c + 1]);
                        atomicMax(&g_gf[(bfirst << 7) + c],     enc_f(y0));
                        atomicMax(&g_gf[(bfirst << 7) + c + 1], enc_f(y1));
                    }
                }
            } else {
                int rstart = 0;
                while (rstart < 32) {
                    const int cur = bix[base + rstart];
                    int rend;
                    if (blast == cur) rend = 32;
                    else {
                        rend = rstart + 1;
                        while (rend < 32 && bix[base + rend] == cur) rend++;
                    }
                    const bool p0 = (rA      >= rstart) && (rA      < rend);
                    const bool p1 = (rA + 8  >= rstart) && (rA + 8  < rend);
                    const bool p2 = (rA + 16 >= rstart) && (rA + 16 < rend);
                    const bool p3 = (rA + 24 >= rstart) && (rA + 24 < rend);
                    float acc[16];
                    #pragma unroll
                    for (int ni = 0; ni < 8; ni++) {
                        float a0 = NEG_INIT, a1 = NEG_INIT;
                        if (p0) { a0 = d[0][ni][0]; a1 = d[0][ni][1]; }
                        if (p1) { a0 = fmaxf(a0, d[0][ni][2]); a1 = fmaxf(a1, d[0][ni][3]); }
                        if (p2) { a0 = fmaxf(a0, d[1][ni][0]); a1 = fmaxf(a1, d[1][ni][1]); }
                        if (p3) { a0 = fmaxf(a0, d[1][ni][2]); a1 = fmaxf(a1, d[1][ni][3]); }
                        acc[2 * ni] = a0; acc[2 * ni + 1] = a1;
                    }
                    #pragma unroll
                    for (int q = 0; q < 16; q++) {
                        acc[q] = fmaxf(acc[q], __shfl_xor_sync(0xFFFFFFFFu, acc[q], 4));
                        acc[q] = fmaxf(acc[q], __shfl_xor_sync(0xFFFFFFFFu, acc[q], 8));
                        acc[q] = fmaxf(acc[q], __shfl_xor_sync(0xFFFFFFFFu, acc[q], 16));
                    }
                    if (lane < 4 && cur >= 0) {
                        #pragma unroll
                        for (int ni = 0; ni < 8; ni++) {
                            const int c = (wn << 6) + (ni << 3) + (lane << 1);
                            float y0 = lrelu(acc[2 * ni]     + b2s[c]);
                            float y1 = lrelu(acc[2 * ni + 1] + b2s[c + 1]);
                            atomicMax(&g_gf[(cur << 7) + c],     enc_f(y0));
                            atomicMax(&g_gf[(cur << 7) + c + 1], enc_f(y1));
                        }
                    }
                    rstart = rend;
                }
            }
        }
        tile += G; it++;
    }
}

// ---------------------------------------------------------------------------
// Decision MLP (round-16 version)
// ---------------------------------------------------------------------------
#define DK_SMEM_FLOATS (16896 + 128 + 128 + 4224)
__global__ __launch_bounds__(128) void decision_kernel(
    const float* __restrict__ cond, const float* __restrict__ W3,
    const float* __restrict__ b3,   const float* __restrict__ W4,
    const float* __restrict__ b4,   float* __restrict__ out, int B)
{
    extern __shared__ float sm[];
    float* W3s   = sm;
    float* b3s   = W3s + 16896;
    float* W4s   = b3s + 128;
    float* in_s  = W4s + 128;
    float* hid_s = in_s;

    const int t = threadIdx.x;
    {
        const float4* src = (const float4*)W3;
        float4* dst = (float4*)W3s;
        #pragma unroll 4
        for (int i = t; i < 4224; i += 128) dst[i] = src[i];
    }
    b3s[t] = b3[t];
    W4s[t] = W4[t];

    const int b0 = blockIdx.x * 32;
    for (int i = t; i < 32 * 132; i += 128) {
        const int bi = i / 132, k = i % 132, bb = b0 + bi;
        float v = 0.f;
        if (bb < B)
            v = (k < 128) ? dec_f(g_gf[bb * 128 + k]) : cond[bb * 4 + (k - 128)];
        in_s[bi * 132 + k] = v;
    }
    __syncthreads();

    const int j = t;
    float acc[32];
    #pragma unroll
    for (int i = 0; i < 32; i++) acc[i] = b3s[j];
    for (int k4 = 0; k4 < 33; k4++) {
        const float w0 = W3s[(4 * k4 + 0) * 128 + j];
        const float w1 = W3s[(4 * k4 + 1) * 128 + j];
        const float w2 = W3s[(4 * k4 + 2) * 128 + j];
        const float w3 = W3s[(4 * k4 + 3) * 128 + j];
        #pragma unroll 8
        for (int i = 0; i < 32; i++) {
            const float4 v = *(const float4*)(in_s + i * 132 + 4 * k4);
            acc[i] += v.x * w0 + v.y * w1 + v.z * w2 + v.w * w3;
        }
    }
    __syncthreads();

    #pragma unroll
    for (int i = 0; i < 32; i++) hid_s[i * 128 + j] = lrelu(acc[i]);
    __syncthreads();

    const int i = t >> 2, g = t & 3;
    float s = 0.f;
    #pragma unroll
    for (int q = 0; q < 32; q++) s += hid_s[i * 128 + g * 32 + q] * W4s[g * 32 + q];
    s += __shfl_down_sync(0xFFFFFFFFu, s, 2, 4);
    s += __shfl_down_sync(0xFFFFFFFFu, s, 1, 4);
    if (g == 0 && (b0 + i) < B) out[b0 + i] = s + b4[0];
}

// ---------------------------------------------------------------------------
extern "C" void kernel_launch(void* const* d_in, const int* in_sizes, int n_in,
                              void* d_out, int out_size)
{
    const float* fm   = (const float*)d_in[0];
    const int*   bi   = (const int*)  d_in[1];
    const float* cond = (const float*)d_in[2];
    const int base = (n_in >= 12) ? 4 : 3;
    const float* W1 = (const float*)d_in[base + 0];
    const float* b1 = (const float*)d_in[base + 1];
    const float* W2 = (const float*)d_in[base + 2];
    const float* b2 = (const float*)d_in[base + 3];
    const float* W3 = (const float*)d_in[base + 4];
    const float* b3 = (const float*)d_in[base + 5];
    const float* W4 = (const float*)d_in[base + 6];
    const float* b4 = (const float*)d_in[base + 7];

    const int N = in_sizes[0] / 3;
    const int B = in_sizes[2] / 4;
    float* out = (float*)d_out;

    cudaFuncSetAttribute(point_kernel,
                         cudaFuncAttributeMaxDynamicSharedMemorySize, SMEM_BYTES);
    const int SMEM_B = DK_SMEM_FLOATS * 4;
    cudaFuncSetAttribute(decision_kernel,
                         cudaFuncAttributeMaxDynamicSharedMemorySize, SMEM_B);

    const int total4 = B * 128 / 4;
    init_gf_kernel<<<(total4 + 255) / 256, 256>>>(total4);

    const int numTiles = (N + 127) / 128;
    point_kernel<<<296, 256, SMEM_BYTES>>>(fm, bi, cond, W1, b1, W2, b2, N, numTiles);

    decision_kernel<<<(B + 31) / 32, 128, SMEM_B>>>(cond, W3, b3, W4, b4, out, B);
}